// round 5
// baseline (speedup 1.0000x reference)
#include <cuda_runtime.h>
#include <cuda_fp16.h>
#include <cstdint>

#define B_    16
#define CIN   512
#define HH    100
#define WW    100
#define HW    10000
#define E_    256
#define TOPK  100

#define SRC_SIZE  (B_ * E_ * HW)
#define POS_OFF   SRC_SIZE
#define POS_SIZE  (B_ * TOPK * E_)
#define TEXT_OFF  (POS_OFF + POS_SIZE)

// ---- scratch (device globals) ----
__device__ float   g_scores[B_ * HW];
__device__ int     g_topk[B_ * TOPK];
__device__ float   g_wbar[CIN];
__device__ float   g_cbar;
__device__ __half  g_convw_h[E_ * CIN];   // fp16 conv_w, [e][c]

// ============================================================
// prep: fp16 weights + wbar/cbar
// ============================================================
__global__ void convh_kernel(const float* __restrict__ conv_w) {
    int i = blockIdx.x * 256 + threadIdx.x;
    g_convw_h[i] = __float2half_rn(conv_w[i]);
}

__global__ void wbar_kernel(const float* __restrict__ conv_w,
                            const float* __restrict__ conv_b) {
    int c = blockIdx.x * 128 + threadIdx.x;
    float s = 0.f;
#pragma unroll 8
    for (int e = 0; e < E_; e++) s += conv_w[e * CIN + c];
    g_wbar[c] = s * (1.f / E_);
    if (blockIdx.x == 0) {
        __shared__ float red[128];
        red[threadIdx.x] = conv_b[threadIdx.x] + conv_b[threadIdx.x + 128];
        __syncthreads();
        for (int s2 = 64; s2 > 0; s2 >>= 1) {
            if (threadIdx.x < s2) red[threadIdx.x] += red[threadIdx.x + s2];
            __syncthreads();
        }
        if (threadIdx.x == 0) g_cbar = red[0] * (1.f / E_);
    }
}

// ============================================================
// main GEMM: fp16 mma m16n8k16 with f16 accum (2x rate hypothesis),
// promoted to f32 every 2 k-tiles. 128pix x 128e x 32k tiles.
// ============================================================
#define TK 32
#define STAGES 4
#define A32_BYTES (TK * 136 * 4)               // 17408  (fp32 [k][136] padded)
#define AH_OFF    A32_BYTES
#define AH_BYTES  (128 * 80)                   // 10240  (fp16 [pix][40] 80B rows)
#define BH_OFF    (AH_OFF + AH_BYTES)
#define BH_BYTES  (128 * 80)                   // 10240  (fp16 [e][40] 80B rows)
#define STAGE_B   (BH_OFF + BH_BYTES)          // 37888
#define WBAR_OFF  (STAGES * STAGE_B)           // 151552
#define BIAS_OFF  (WBAR_OFF + CIN * 4)
#define SRED_OFF  (BIAS_OFF + 512)
#define SMEM_TOTAL (SRED_OFF + 1024)           // 155136

__device__ __forceinline__ uint32_t pack_h2(float lo, float hi) {
    uint32_t d;
    asm("cvt.rn.f16x2.f32 %0, %1, %2;" : "=r"(d) : "f"(hi), "f"(lo));
    return d;
}

__device__ __forceinline__ void mma_f16acc(uint32_t* c, const uint32_t* a,
                                           const uint32_t* b) {
    asm volatile(
        "mma.sync.aligned.m16n8k16.row.col.f16.f16.f16.f16 "
        "{%0,%1}, {%2,%3,%4,%5}, {%6,%7}, {%0,%1};\n"
        : "+r"(c[0]), "+r"(c[1])
        : "r"(a[0]), "r"(a[1]), "r"(a[2]), "r"(a[3]), "r"(b[0]), "r"(b[1]));
}

__global__ void __launch_bounds__(256, 1)
gemm_kernel(const float* __restrict__ feat,
            const float* __restrict__ conv_b,
            float* __restrict__ out) {
    extern __shared__ char smem[];
    const int eTile = blockIdx.x;                 // 0..1 fastest -> L2 reuse of A
    const int pt    = blockIdx.y;                 // 0..1263
    const int b     = pt / 79;
    const int p0    = (pt % 79) * 128;
    const int valid = min(128, HW - p0);
    const int e0    = eTile * 128;
    const int tid   = threadIdx.x;
    const int warp  = tid >> 5, lane = tid & 31;
    const int wm = (warp & 1) * 64;               // pixel offset of warp tile
    const int wn = (warp >> 1) * 32;              // e offset of warp tile

    float* s_wbar = (float*)(smem + WBAR_OFF);
    float* s_bias = (float*)(smem + BIAS_OFF);
    float* s_red  = (float*)(smem + SRED_OFF);
    if (tid < 128) s_bias[tid] = conv_b[e0 + tid];
    s_wbar[tid]       = g_wbar[tid];
    s_wbar[tid + 256] = g_wbar[tid + 256];

    const float* gA = feat + (size_t)b * CIN * HW + p0;
    const __half* gB = g_convw_h + (size_t)e0 * CIN;

    auto issue_stage = [&](int slot, int kt) {
        char* base = smem + slot * STAGE_B;
        int c0 = kt * TK;
#pragma unroll
        for (int i = 0; i < 4; i++) {                 // A fp32: 32k x 128pix
            int cid = tid + i * 256;
            int k  = cid >> 5;
            int pc = (cid & 31) << 2;
            const float* src = gA + (size_t)(c0 + k) * HW + pc;
            uint32_t dst = (uint32_t)__cvta_generic_to_shared(base + k * 544 + pc * 4);
            int sz = (pc < valid) ? 16 : 0;
            asm volatile("cp.async.cg.shared.global [%0], [%1], 16, %2;\n"
                         :: "r"(dst), "l"(src), "r"(sz) : "memory");
        }
#pragma unroll
        for (int i = 0; i < 2; i++) {                 // B fp16: 128e x 32k
            int cid = tid + i * 256;
            int e   = cid >> 2;
            int c16 = cid & 3;
            const __half* src = gB + (size_t)e * CIN + c0 + c16 * 8;
            uint32_t dst = (uint32_t)__cvta_generic_to_shared(
                base + BH_OFF + e * 80 + c16 * 16);
            asm volatile("cp.async.cg.shared.global [%0], [%1], 16;\n"
                         :: "r"(dst), "l"(src) : "memory");
        }
    };

    float acc[4][4][4];
    uint32_t acch[4][4][2];
#pragma unroll
    for (int mf = 0; mf < 4; mf++)
#pragma unroll
        for (int nf = 0; nf < 4; nf++) {
#pragma unroll
            for (int r = 0; r < 4; r++) acc[mf][nf][r] = 0.f;
            acch[mf][nf][0] = 0u; acch[mf][nf][1] = 0u;
        }

    float scoreAcc = 0.f;
    const int m_cv = tid & 127;                   // pixel this thread converts
    const int kh   = tid >> 7;                    // k-half (0 or 1)

    issue_stage(0, 0); asm volatile("cp.async.commit_group;\n" ::: "memory");
    issue_stage(1, 1); asm volatile("cp.async.commit_group;\n" ::: "memory");
    issue_stage(2, 2); asm volatile("cp.async.commit_group;\n" ::: "memory");

    for (int kt = 0; kt < 16; kt++) {
        const int slot = kt & 3;
        char* base = smem + slot * STAGE_B;
        asm volatile("cp.async.wait_group 2;\n" ::: "memory");
        __syncthreads();

        // ---- convert A fp32 [k][pix] -> fp16 [pix][k] (+ fused fp32 score) ----
        {
            const float* a32 = (const float*)(base) + kh * 16 * 136 + m_cv;
            const float* wb  = s_wbar + kt * TK + kh * 16;
            float v[16];
#pragma unroll
            for (int k = 0; k < 16; k++) v[k] = a32[k * 136];
#pragma unroll
            for (int k = 0; k < 16; k++) scoreAcc += v[k] * wb[k];
            uint32_t h2[8];
#pragma unroll
            for (int j = 0; j < 8; j++) h2[j] = pack_h2(v[2 * j], v[2 * j + 1]);
            uint4* dst = (uint4*)(base + AH_OFF + m_cv * 80 + kh * 32);
            dst[0] = make_uint4(h2[0], h2[1], h2[2], h2[3]);
            dst[1] = make_uint4(h2[4], h2[5], h2[6], h2[7]);
        }
        __syncthreads();

        // ---- mma phase: 2 ksteps of k16, f16 accum ----
        const char* ah = base + AH_OFF;
        const char* bh = base + BH_OFF;
#pragma unroll
        for (int ks = 0; ks < 2; ks++) {
            const int kb = ks * 32 + (lane & 3) * 4;   // byte offset of k pair
            uint32_t afr[4][4];
#pragma unroll
            for (int mf = 0; mf < 4; mf++) {
                int r = wm + mf * 16 + (lane >> 2);
                afr[mf][0] = *(const uint32_t*)(ah + r * 80 + kb);
                afr[mf][1] = *(const uint32_t*)(ah + (r + 8) * 80 + kb);
                afr[mf][2] = *(const uint32_t*)(ah + r * 80 + kb + 16);
                afr[mf][3] = *(const uint32_t*)(ah + (r + 8) * 80 + kb + 16);
            }
            uint32_t bfr[4][2];
#pragma unroll
            for (int nf = 0; nf < 4; nf++) {
                int n = wn + nf * 8 + (lane >> 2);
                bfr[nf][0] = *(const uint32_t*)(bh + n * 80 + kb);
                bfr[nf][1] = *(const uint32_t*)(bh + n * 80 + kb + 16);
            }
#pragma unroll
            for (int mf = 0; mf < 4; mf++)
#pragma unroll
                for (int nf = 0; nf < 4; nf++)
                    mma_f16acc(acch[mf][nf], afr[mf], bfr[nf]);
        }

        // ---- promote f16 partials to f32 every 2 k-tiles ----
        if (kt & 1) {
#pragma unroll
            for (int mf = 0; mf < 4; mf++)
#pragma unroll
                for (int nf = 0; nf < 4; nf++) {
                    float2 f0 = __half22float2(*(const __half2*)&acch[mf][nf][0]);
                    float2 f1 = __half22float2(*(const __half2*)&acch[mf][nf][1]);
                    acc[mf][nf][0] += f0.x; acc[mf][nf][1] += f0.y;
                    acc[mf][nf][2] += f1.x; acc[mf][nf][3] += f1.y;
                    acch[mf][nf][0] = 0u; acch[mf][nf][1] = 0u;
                }
        }

        __syncthreads();
        if (kt + 3 < 16) issue_stage((kt + 3) & 3, kt + 3);
        asm volatile("cp.async.commit_group;\n" ::: "memory");
    }

    // ---- combine the two k-half score accumulators ----
    s_red[tid] = scoreAcc;
    __syncthreads();
    if (eTile == 0 && tid < valid)
        g_scores[b * HW + p0 + tid] = s_red[tid] + s_red[tid + 128] + g_cbar;

    // ---- epilogue ----
    float* outp = out + (size_t)b * E_ * HW + p0;
#pragma unroll
    for (int mf = 0; mf < 4; mf++) {
        int r0 = wm + mf * 16 + (lane >> 2);
#pragma unroll
        for (int nf = 0; nf < 4; nf++) {
            int c0 = wn + nf * 8 + (lane & 3) * 2;
            float b0v = s_bias[c0], b1v = s_bias[c0 + 1];
            if (r0 < valid) {
                outp[(size_t)(e0 + c0)     * HW + r0] = acc[mf][nf][0] + b0v;
                outp[(size_t)(e0 + c0 + 1) * HW + r0] = acc[mf][nf][1] + b1v;
            }
            if (r0 + 8 < valid) {
                outp[(size_t)(e0 + c0)     * HW + r0 + 8] = acc[mf][nf][2] + b0v;
                outp[(size_t)(e0 + c0 + 1) * HW + r0 + 8] = acc[mf][nf][3] + b1v;
            }
        }
    }
}

// ============================================================
// per-batch top-100 via radix select, parallel bin scans
// ============================================================
#define TPB 1024
__global__ void __launch_bounds__(TPB) topk_kernel() {
    __shared__ uint32_t skey[HW];
    __shared__ int hist[256];
    __shared__ int sscan[256];
    __shared__ int s_pref, s_need, s_cnt, s_idxT;
    __shared__ uint32_t wkey[128];
    __shared__ uint32_t widx[128];

    const int b = blockIdx.x, tid = threadIdx.x;
    const float* sc = g_scores + b * HW;
    for (int i = tid; i < HW; i += TPB) {
        uint32_t bits = __float_as_uint(sc[i]);
        skey[i] = (bits & 0x80000000u) ? ~bits : (bits | 0x80000000u);
    }
    __syncthreads();

    // ---- 4x 8-bit radix passes (parallel suffix scan over bins) ----
    uint32_t prefVal = 0, prefMask = 0;
    int need = TOPK;
    for (int pass = 0; pass < 4; pass++) {
        int shift = 24 - 8 * pass;
        if (tid < 256) hist[tid] = 0;
        __syncthreads();
        for (int i = tid; i < HW; i += TPB) {
            uint32_t k = skey[i];
            if ((k & prefMask) == prefVal)
                atomicAdd(&hist[(k >> shift) & 255], 1);
        }
        __syncthreads();
        if (tid < 256) sscan[tid] = hist[tid];
        __syncthreads();
#pragma unroll
        for (int st = 1; st < 256; st <<= 1) {        // inclusive suffix scan
            int add = (tid < 256 && tid + st < 256) ? sscan[tid + st] : 0;
            __syncthreads();
            if (tid < 256) sscan[tid] += add;
            __syncthreads();
        }
        if (tid < 256) {
            int sfx = sscan[tid], cnt = hist[tid];
            if (sfx >= need && sfx - cnt < need) {    // exactly one bin
                s_pref = tid;
                s_need = need - (sfx - cnt);
            }
        }
        __syncthreads();
        prefVal |= ((uint32_t)s_pref) << shift;
        prefMask |= 0xFFu << shift;
        need = s_need;
        __syncthreads();
    }
    const uint32_t uT = prefVal;
    const int T = need;   // ties (key == uT) to take, smallest index first

    // ---- pass A: coarse index bin (128 bins of 128 idx) ----
    if (tid < 256) hist[tid] = 0;
    __syncthreads();
    for (int i = tid; i < HW; i += TPB)
        if (skey[i] == uT) atomicAdd(&hist[i >> 7], 1);
    __syncthreads();
    if (tid < 256) sscan[tid] = (tid < 128) ? hist[tid] : 0;
    __syncthreads();
#pragma unroll
    for (int st = 1; st < 128; st <<= 1) {            // inclusive prefix scan
        int add = (tid < 128 && tid >= st) ? sscan[tid - st] : 0;
        __syncthreads();
        if (tid < 128) sscan[tid] += add;
        __syncthreads();
    }
    if (tid < 128) {
        int pfx = sscan[tid], cnt = hist[tid];
        if (pfx >= T && pfx - cnt < T) {
            s_pref = tid;
            s_need = T - (pfx - cnt);
        }
    }
    __syncthreads();
    const int binA = s_pref, Trem = s_need;

    // ---- pass B: fine index within coarse bin ----
    if (tid < 256) hist[tid] = 0;
    __syncthreads();
    for (int i = tid; i < HW; i += TPB)
        if (skey[i] == uT && (i >> 7) == binA) atomicAdd(&hist[i & 127], 1);
    __syncthreads();
    if (tid < 256) sscan[tid] = (tid < 128) ? hist[tid] : 0;
    __syncthreads();
#pragma unroll
    for (int st = 1; st < 128; st <<= 1) {
        int add = (tid < 128 && tid >= st) ? sscan[tid - st] : 0;
        __syncthreads();
        if (tid < 128) sscan[tid] += add;
        __syncthreads();
    }
    if (tid < 128) {
        int pfx = sscan[tid], cnt = hist[tid];
        if (pfx >= Trem && pfx - cnt < Trem) {
            s_idxT = binA * 128 + tid;
            s_cnt = 0;
        }
    }
    __syncthreads();
    const int idxT = s_idxT;

    // ---- collect the exact 100 winners ----
    for (int i = tid; i < HW; i += TPB) {
        uint32_t k = skey[i];
        if (k > uT || (k == uT && i <= idxT)) {
            int p = atomicAdd(&s_cnt, 1);
            wkey[p] = k;
            widx[p] = (uint32_t)i;
        }
    }
    __syncthreads();
    if (tid >= TOPK && tid < 128) { wkey[tid] = 0; widx[tid] = 0xFFFFFFFFu; }
    __syncthreads();

    // ---- bitonic sort 128 slots, ascending by (key, ~idx) ----
    for (int size = 2; size <= 128; size <<= 1) {
        for (int stride = size >> 1; stride > 0; stride >>= 1) {
            __syncthreads();
            if (tid < 128) {
                int j = tid ^ stride;
                if (j > tid) {
                    uint64_t ki = ((uint64_t)wkey[tid] << 32) | (uint32_t)(~widx[tid]);
                    uint64_t kj = ((uint64_t)wkey[j]   << 32) | (uint32_t)(~widx[j]);
                    bool up = ((tid & size) == 0);
                    if ((ki > kj) == up) {
                        uint32_t t;
                        t = wkey[tid]; wkey[tid] = wkey[j]; wkey[j] = t;
                        t = widx[tid]; widx[tid] = widx[j]; widx[j] = t;
                    }
                }
            }
        }
    }
    __syncthreads();
    if (tid < TOPK) g_topk[b * TOPK + tid] = (int)widx[127 - tid];
}

// ============================================================
// tail: pos_embed + text_proj
// ============================================================
__global__ void tail_kernel(const float* __restrict__ coord_w,
                            const float* __restrict__ coord_b,
                            const float* __restrict__ text_emb,
                            const float* __restrict__ text_w,
                            const float* __restrict__ text_b,
                            float* __restrict__ out) {
    __shared__ float red[256];
    int blk = blockIdx.x, tid = threadIdx.x;
    if (blk < B_ * TOPK) {
        int b = blk / TOPK, k = blk % TOPK;
        int idx = g_topk[b * TOPK + k];
        float ys = (float)(idx / WW) / (float)HH;
        float xs = (float)(idx % WW) / (float)WW;
        float v = xs * coord_w[tid * 2 + 0] + ys * coord_w[tid * 2 + 1] + coord_b[tid];
        out[POS_OFF + (size_t)(b * TOPK + k) * E_ + tid] = v;
    } else {
        int e = blk - B_ * TOPK;
        float s = 0.f;
        for (int i = tid; i < 786; i += 256) s += text_emb[i] * text_w[e * 786 + i];
        red[tid] = s; __syncthreads();
        for (int k2 = 128; k2 > 0; k2 >>= 1) {
            if (tid < k2) red[tid] += red[tid + k2];
            __syncthreads();
        }
        if (tid == 0) {
            float v = red[0] + text_b[e];
            for (int bb = 0; bb < B_; bb++) out[TEXT_OFF + bb * E_ + e] = v;
        }
    }
}

// ============================================================
extern "C" void kernel_launch(void* const* d_in, const int* in_sizes, int n_in,
                              void* d_out, int out_size) {
    const float* feat     = (const float*)d_in[0];
    const float* text_emb = (const float*)d_in[2];
    const float* conv_w   = (const float*)d_in[3];
    const float* conv_b   = (const float*)d_in[4];
    const float* text_w   = (const float*)d_in[5];
    const float* text_b   = (const float*)d_in[6];
    const float* coord_w  = (const float*)d_in[7];
    const float* coord_b  = (const float*)d_in[8];
    float* out = (float*)d_out;

    cudaFuncSetAttribute(gemm_kernel,
                         cudaFuncAttributeMaxDynamicSharedMemorySize, SMEM_TOTAL);

    convh_kernel<<<E_ * CIN / 256, 256>>>(conv_w);
    wbar_kernel<<<4, 128>>>(conv_w, conv_b);
    dim3 g(2, 1264);
    gemm_kernel<<<g, 256, SMEM_TOTAL>>>(feat, conv_b, out);
    topk_kernel<<<B_, TPB>>>();
    tail_kernel<<<B_ * TOPK + E_, 256>>>(coord_w, coord_b,
                                         text_emb, text_w, text_b, out);
}

// round 6
// speedup vs baseline: 1.3193x; 1.3193x over previous
#include <cuda_runtime.h>
#include <cuda_fp16.h>
#include <cstdint>

#define B_    16
#define CIN   512
#define HH    100
#define WW    100
#define HW    10000
#define E_    256
#define TOPK  100

#define SRC_SIZE  (B_ * E_ * HW)
#define POS_OFF   SRC_SIZE
#define POS_SIZE  (B_ * TOPK * E_)
#define TEXT_OFF  (POS_OFF + POS_SIZE)

// ---- scratch (device globals) ----
__device__ float   g_scores[B_ * HW];
__device__ int     g_topk[B_ * TOPK];
__device__ float   g_wbar[CIN];
__device__ float   g_cbar;
__device__ __half  g_convw_h[E_ * CIN];   // fp16 conv_w, [e][c]

// ============================================================
// prep: fp16 weights + wbar/cbar
// ============================================================
__global__ void convh_kernel(const float* __restrict__ conv_w) {
    int i = blockIdx.x * 256 + threadIdx.x;
    g_convw_h[i] = __float2half_rn(conv_w[i]);
}

__global__ void wbar_kernel(const float* __restrict__ conv_w,
                            const float* __restrict__ conv_b) {
    int c = blockIdx.x * 128 + threadIdx.x;
    float s = 0.f;
#pragma unroll 8
    for (int e = 0; e < E_; e++) s += conv_w[e * CIN + c];
    g_wbar[c] = s * (1.f / E_);
    if (blockIdx.x == 0) {
        __shared__ float red[128];
        red[threadIdx.x] = conv_b[threadIdx.x] + conv_b[threadIdx.x + 128];
        __syncthreads();
        for (int s2 = 64; s2 > 0; s2 >>= 1) {
            if (threadIdx.x < s2) red[threadIdx.x] += red[threadIdx.x + s2];
            __syncthreads();
        }
        if (threadIdx.x == 0) g_cbar = red[0] * (1.f / E_);
    }
}

// ============================================================
// main GEMM: fp16 mma m16n8k16, f32 accum; 128pix x 128e x 32k
// smem 107KB -> 2 CTAs/SM; cross-CTA phase overlap
// ============================================================
#define TK 32
#define A32_ST 17408                       // fp32 [32k][136pix] padded
#define AH_ST  10240                       // fp16 [128pix][40k] 80B rows
#define BH_ST  10240                       // fp16 [128e][40k] 80B rows
#define A32_OFF 0                          // 3 slots
#define AH_OFF  (3 * A32_ST)               // 52224, 2 slots
#define BH_OFF  (AH_OFF + 2 * AH_ST)       // 72704, 3 slots
#define WBAR_OFF (BH_OFF + 3 * BH_ST)      // 103424
#define BIAS_OFF (WBAR_OFF + CIN * 4)      // 105472
#define SRED_OFF (BIAS_OFF + 512)          // 105984
#define SMEM_TOTAL (SRED_OFF + 1024)       // 107008

__device__ __forceinline__ uint32_t pack_h2(float lo, float hi) {
    uint32_t d;
    asm("cvt.rn.f16x2.f32 %0, %1, %2;" : "=r"(d) : "f"(hi), "f"(lo));
    return d;
}

__device__ __forceinline__ void mma_f16(float* c, const uint32_t* a, const uint32_t* b) {
    asm volatile(
        "mma.sync.aligned.m16n8k16.row.col.f32.f16.f16.f32 "
        "{%0,%1,%2,%3}, {%4,%5,%6,%7}, {%8,%9}, {%0,%1,%2,%3};\n"
        : "+f"(c[0]), "+f"(c[1]), "+f"(c[2]), "+f"(c[3])
        : "r"(a[0]), "r"(a[1]), "r"(a[2]), "r"(a[3]), "r"(b[0]), "r"(b[1]));
}

__global__ void __launch_bounds__(256, 2)
gemm_kernel(const float* __restrict__ feat,
            const float* __restrict__ conv_b,
            float* __restrict__ out) {
    extern __shared__ char smem[];
    const int eTile = blockIdx.x;                 // 0..1 fastest -> L2 reuse of A
    const int pt    = blockIdx.y;                 // 0..1263
    const int b     = pt / 79;
    const int p0    = (pt % 79) * 128;
    const int valid = min(128, HW - p0);
    const int e0    = eTile * 128;
    const int tid   = threadIdx.x;
    const int warp  = tid >> 5, lane = tid & 31;
    const int wm = (warp & 1) * 64;               // pixel offset of warp tile
    const int wn = (warp >> 1) * 32;              // e offset of warp tile

    float* s_wbar = (float*)(smem + WBAR_OFF);
    float* s_bias = (float*)(smem + BIAS_OFF);
    float* s_red  = (float*)(smem + SRED_OFF);
    if (tid < 128) s_bias[tid] = conv_b[e0 + tid];
    s_wbar[tid]       = g_wbar[tid];
    s_wbar[tid + 256] = g_wbar[tid + 256];

    const float* gA = feat + (size_t)b * CIN * HW + p0;
    const __half* gB = g_convw_h + (size_t)e0 * CIN;

    auto issue_stage = [&](int slot, int kt) {
        char* baseA = smem + A32_OFF + slot * A32_ST;
        char* baseB = smem + BH_OFF + slot * BH_ST;
        int c0 = kt * TK;
#pragma unroll
        for (int i = 0; i < 4; i++) {                 // A fp32: 32k x 128pix
            int cid = tid + i * 256;
            int k  = cid >> 5;
            int pc = (cid & 31) << 2;
            const float* src = gA + (size_t)(c0 + k) * HW + pc;
            uint32_t dst = (uint32_t)__cvta_generic_to_shared(baseA + k * 544 + pc * 4);
            int sz = (pc < valid) ? 16 : 0;
            asm volatile("cp.async.cg.shared.global [%0], [%1], 16, %2;\n"
                         :: "r"(dst), "l"(src), "r"(sz) : "memory");
        }
#pragma unroll
        for (int i = 0; i < 2; i++) {                 // B fp16: 128e x 32k
            int cid = tid + i * 256;
            int e   = cid >> 2;
            int c16 = cid & 3;
            const __half* src = gB + (size_t)e * CIN + c0 + c16 * 8;
            uint32_t dst = (uint32_t)__cvta_generic_to_shared(baseB + e * 80 + c16 * 16);
            asm volatile("cp.async.cg.shared.global [%0], [%1], 16;\n"
                         :: "r"(dst), "l"(src) : "memory");
        }
    };

    float acc[4][4][4];
#pragma unroll
    for (int mf = 0; mf < 4; mf++)
#pragma unroll
        for (int nf = 0; nf < 4; nf++)
#pragma unroll
            for (int r = 0; r < 4; r++) acc[mf][nf][r] = 0.f;

    float scoreAcc = 0.f;
    const int m_cv = tid & 127;                   // pixel this thread converts
    const int kh   = tid >> 7;                    // k-half (0 or 1)

    issue_stage(0, 0); asm volatile("cp.async.commit_group;\n" ::: "memory");
    issue_stage(1, 1); asm volatile("cp.async.commit_group;\n" ::: "memory");

    int slot = 0;       // kt % 3
    for (int kt = 0; kt < 16; kt++) {
        __syncthreads();                          // all reads of slot (kt+2)%3 done
        int nslot = slot + 2; if (nslot >= 3) nslot -= 3;
        if (kt + 2 < 16) issue_stage(nslot, kt + 2);
        asm volatile("cp.async.commit_group;\n" ::: "memory");
        asm volatile("cp.async.wait_group 2;\n" ::: "memory");
        __syncthreads();                          // stage kt visible to all

        // ---- convert A fp32 [k][pix] -> fp16 [pix][k] (+ fused fp32 score) ----
        char* baseA  = smem + A32_OFF + slot * A32_ST;
        char* baseAH = smem + AH_OFF + (kt & 1) * AH_ST;
        {
            const float* a32 = (const float*)baseA + kh * 16 * 136 + m_cv;
            const float* wb  = s_wbar + kt * TK + kh * 16;
            float v[16];
#pragma unroll
            for (int k = 0; k < 16; k++) v[k] = a32[k * 136];
#pragma unroll
            for (int k = 0; k < 16; k++) scoreAcc += v[k] * wb[k];
            uint32_t h2[8];
#pragma unroll
            for (int j = 0; j < 8; j++) h2[j] = pack_h2(v[2 * j], v[2 * j + 1]);
            uint4* dst = (uint4*)(baseAH + m_cv * 80 + kh * 32);
            dst[0] = make_uint4(h2[0], h2[1], h2[2], h2[3]);
            dst[1] = make_uint4(h2[4], h2[5], h2[6], h2[7]);
        }
        __syncthreads();                          // AH ready

        // ---- mma phase: 2 ksteps of k16, f32 accum ----
        const char* ah = baseAH;
        const char* bh = smem + BH_OFF + slot * BH_ST;
#pragma unroll
        for (int ks = 0; ks < 2; ks++) {
            const int kb = ks * 32 + (lane & 3) * 4;   // byte offset of k pair
            uint32_t afr[4][4];
#pragma unroll
            for (int mf = 0; mf < 4; mf++) {
                int r = wm + mf * 16 + (lane >> 2);
                afr[mf][0] = *(const uint32_t*)(ah + r * 80 + kb);
                afr[mf][1] = *(const uint32_t*)(ah + (r + 8) * 80 + kb);
                afr[mf][2] = *(const uint32_t*)(ah + r * 80 + kb + 16);
                afr[mf][3] = *(const uint32_t*)(ah + (r + 8) * 80 + kb + 16);
            }
            uint32_t bfr[4][2];
#pragma unroll
            for (int nf = 0; nf < 4; nf++) {
                int n = wn + nf * 8 + (lane >> 2);
                bfr[nf][0] = *(const uint32_t*)(bh + n * 80 + kb);
                bfr[nf][1] = *(const uint32_t*)(bh + n * 80 + kb + 16);
            }
#pragma unroll
            for (int mf = 0; mf < 4; mf++)
#pragma unroll
                for (int nf = 0; nf < 4; nf++)
                    mma_f16(acc[mf][nf], afr[mf], bfr[nf]);
        }

        if (++slot >= 3) slot -= 3;
    }

    // ---- combine the two k-half score accumulators ----
    s_red[tid] = scoreAcc;
    __syncthreads();
    if (eTile == 0 && tid < valid)
        g_scores[b * HW + p0 + tid] = s_red[tid] + s_red[tid + 128] + g_cbar;

    // ---- epilogue ----
    float* outp = out + (size_t)b * E_ * HW + p0;
#pragma unroll
    for (int mf = 0; mf < 4; mf++) {
        int r0 = wm + mf * 16 + (lane >> 2);
#pragma unroll
        for (int nf = 0; nf < 4; nf++) {
            int c0 = wn + nf * 8 + (lane & 3) * 2;
            float b0v = s_bias[c0], b1v = s_bias[c0 + 1];
            if (r0 < valid) {
                outp[(size_t)(e0 + c0)     * HW + r0] = acc[mf][nf][0] + b0v;
                outp[(size_t)(e0 + c0 + 1) * HW + r0] = acc[mf][nf][1] + b1v;
            }
            if (r0 + 8 < valid) {
                outp[(size_t)(e0 + c0)     * HW + r0 + 8] = acc[mf][nf][2] + b0v;
                outp[(size_t)(e0 + c0 + 1) * HW + r0 + 8] = acc[mf][nf][3] + b1v;
            }
        }
    }
}

// ============================================================
// per-batch top-100 via radix select, parallel bin scans
// ============================================================
#define TPB 1024
__global__ void __launch_bounds__(TPB) topk_kernel() {
    __shared__ uint32_t skey[HW];
    __shared__ int hist[256];
    __shared__ int sscan[256];
    __shared__ int s_pref, s_need, s_cnt, s_idxT;
    __shared__ uint32_t wkey[128];
    __shared__ uint32_t widx[128];

    const int b = blockIdx.x, tid = threadIdx.x;
    const float* sc = g_scores + b * HW;
    for (int i = tid; i < HW; i += TPB) {
        uint32_t bits = __float_as_uint(sc[i]);
        skey[i] = (bits & 0x80000000u) ? ~bits : (bits | 0x80000000u);
    }
    __syncthreads();

    uint32_t prefVal = 0, prefMask = 0;
    int need = TOPK;
    for (int pass = 0; pass < 4; pass++) {
        int shift = 24 - 8 * pass;
        if (tid < 256) hist[tid] = 0;
        __syncthreads();
        for (int i = tid; i < HW; i += TPB) {
            uint32_t k = skey[i];
            if ((k & prefMask) == prefVal)
                atomicAdd(&hist[(k >> shift) & 255], 1);
        }
        __syncthreads();
        if (tid < 256) sscan[tid] = hist[tid];
        __syncthreads();
#pragma unroll
        for (int st = 1; st < 256; st <<= 1) {        // inclusive suffix scan
            int add = (tid < 256 && tid + st < 256) ? sscan[tid + st] : 0;
            __syncthreads();
            if (tid < 256) sscan[tid] += add;
            __syncthreads();
        }
        if (tid < 256) {
            int sfx = sscan[tid], cnt = hist[tid];
            if (sfx >= need && sfx - cnt < need) {
                s_pref = tid;
                s_need = need - (sfx - cnt);
            }
        }
        __syncthreads();
        prefVal |= ((uint32_t)s_pref) << shift;
        prefMask |= 0xFFu << shift;
        need = s_need;
        __syncthreads();
    }
    const uint32_t uT = prefVal;
    const int T = need;

    if (tid < 256) hist[tid] = 0;
    __syncthreads();
    for (int i = tid; i < HW; i += TPB)
        if (skey[i] == uT) atomicAdd(&hist[i >> 7], 1);
    __syncthreads();
    if (tid < 256) sscan[tid] = (tid < 128) ? hist[tid] : 0;
    __syncthreads();
#pragma unroll
    for (int st = 1; st < 128; st <<= 1) {
        int add = (tid < 128 && tid >= st) ? sscan[tid - st] : 0;
        __syncthreads();
        if (tid < 128) sscan[tid] += add;
        __syncthreads();
    }
    if (tid < 128) {
        int pfx = sscan[tid], cnt = hist[tid];
        if (pfx >= T && pfx - cnt < T) {
            s_pref = tid;
            s_need = T - (pfx - cnt);
        }
    }
    __syncthreads();
    const int binA = s_pref, Trem = s_need;

    if (tid < 256) hist[tid] = 0;
    __syncthreads();
    for (int i = tid; i < HW; i += TPB)
        if (skey[i] == uT && (i >> 7) == binA) atomicAdd(&hist[i & 127], 1);
    __syncthreads();
    if (tid < 256) sscan[tid] = (tid < 128) ? hist[tid] : 0;
    __syncthreads();
#pragma unroll
    for (int st = 1; st < 128; st <<= 1) {
        int add = (tid < 128 && tid >= st) ? sscan[tid - st] : 0;
        __syncthreads();
        if (tid < 128) sscan[tid] += add;
        __syncthreads();
    }
    if (tid < 128) {
        int pfx = sscan[tid], cnt = hist[tid];
        if (pfx >= Trem && pfx - cnt < Trem) {
            s_idxT = binA * 128 + tid;
            s_cnt = 0;
        }
    }
    __syncthreads();
    const int idxT = s_idxT;

    for (int i = tid; i < HW; i += TPB) {
        uint32_t k = skey[i];
        if (k > uT || (k == uT && i <= idxT)) {
            int p = atomicAdd(&s_cnt, 1);
            wkey[p] = k;
            widx[p] = (uint32_t)i;
        }
    }
    __syncthreads();
    if (tid >= TOPK && tid < 128) { wkey[tid] = 0; widx[tid] = 0xFFFFFFFFu; }
    __syncthreads();

    for (int size = 2; size <= 128; size <<= 1) {
        for (int stride = size >> 1; stride > 0; stride >>= 1) {
            __syncthreads();
            if (tid < 128) {
                int j = tid ^ stride;
                if (j > tid) {
                    uint64_t ki = ((uint64_t)wkey[tid] << 32) | (uint32_t)(~widx[tid]);
                    uint64_t kj = ((uint64_t)wkey[j]   << 32) | (uint32_t)(~widx[j]);
                    bool up = ((tid & size) == 0);
                    if ((ki > kj) == up) {
                        uint32_t t;
                        t = wkey[tid]; wkey[tid] = wkey[j]; wkey[j] = t;
                        t = widx[tid]; widx[tid] = widx[j]; widx[j] = t;
                    }
                }
            }
        }
    }
    __syncthreads();
    if (tid < TOPK) g_topk[b * TOPK + tid] = (int)widx[127 - tid];
}

// ============================================================
// tail: pos_embed + text_proj
// ============================================================
__global__ void tail_kernel(const float* __restrict__ coord_w,
                            const float* __restrict__ coord_b,
                            const float* __restrict__ text_emb,
                            const float* __restrict__ text_w,
                            const float* __restrict__ text_b,
                            float* __restrict__ out) {
    __shared__ float red[256];
    int blk = blockIdx.x, tid = threadIdx.x;
    if (blk < B_ * TOPK) {
        int b = blk / TOPK, k = blk % TOPK;
        int idx = g_topk[b * TOPK + k];
        float ys = (float)(idx / WW) / (float)HH;
        float xs = (float)(idx % WW) / (float)WW;
        float v = xs * coord_w[tid * 2 + 0] + ys * coord_w[tid * 2 + 1] + coord_b[tid];
        out[POS_OFF + (size_t)(b * TOPK + k) * E_ + tid] = v;
    } else {
        int e = blk - B_ * TOPK;
        float s = 0.f;
        for (int i = tid; i < 786; i += 256) s += text_emb[i] * text_w[e * 786 + i];
        red[tid] = s; __syncthreads();
        for (int k2 = 128; k2 > 0; k2 >>= 1) {
            if (tid < k2) red[tid] += red[tid + k2];
            __syncthreads();
        }
        if (tid == 0) {
            float v = red[0] + text_b[e];
            for (int bb = 0; bb < B_; bb++) out[TEXT_OFF + bb * E_ + e] = v;
        }
    }
}

// ============================================================
extern "C" void kernel_launch(void* const* d_in, const int* in_sizes, int n_in,
                              void* d_out, int out_size) {
    const float* feat     = (const float*)d_in[0];
    const float* text_emb = (const float*)d_in[2];
    const float* conv_w   = (const float*)d_in[3];
    const float* conv_b   = (const float*)d_in[4];
    const float* text_w   = (const float*)d_in[5];
    const float* text_b   = (const float*)d_in[6];
    const float* coord_w  = (const float*)d_in[7];
    const float* coord_b  = (const float*)d_in[8];
    float* out = (float*)d_out;

    cudaFuncSetAttribute(gemm_kernel,
                         cudaFuncAttributeMaxDynamicSharedMemorySize, SMEM_TOTAL);

    convh_kernel<<<E_ * CIN / 256, 256>>>(conv_w);
    wbar_kernel<<<4, 128>>>(conv_w, conv_b);
    dim3 g(2, 1264);
    gemm_kernel<<<g, 256, SMEM_TOTAL>>>(feat, conv_b, out);
    topk_kernel<<<B_, TPB>>>();
    tail_kernel<<<B_ * TOPK + E_, 256>>>(coord_w, coord_b,
                                         text_emb, text_w, text_b, out);
}